// round 12
// baseline (speedup 1.0000x reference)
#include <cuda_runtime.h>
#include <cuda_fp16.h>
#include <cstdint>

#define NN   4096
#define FF   256
#define KH   8
#define FPD  64
#define KFP  512   // K*FP
#define LOG2E 1.4426950408889634f

// ---------------- scratch (static device globals; no allocation) -------------
__device__ float g_hl[KH * NN];                   // hl[k][n] * log2(e)
__device__ uint2 g_hrB[KH * NN / 2];              // packed { fp16x2(B,B'), fp16x2(B2,B2') } pairs
__device__ int g_mask_fmt;                        // 0=uint8, else 4-byte words
__device__ unsigned short g_maskh[NN * NN];       // 32 MB fp16 mask (1.0 / 0.0)
__device__ unsigned short g_xeT_h[KH * FPD * NN]; // 4 MB: fp16(xe)[k][f][n]

// =================== helpers (baseline PTX only) ============================
__device__ __forceinline__ uint32_t smem_u32(const void* p) {
    uint32_t a;
    asm("{ .reg .u64 t; cvta.to.shared.u64 t, %1; cvt.u32.u64 %0, t; }" : "=r"(a) : "l"(p));
    return a;
}
__device__ __forceinline__ uint32_t h16x2(float x, float y) {
    uint32_t r;
    asm("cvt.rn.f16x2.f32 %0, %1, %2;" : "=r"(r) : "f"(y), "f"(x));
    return r;
}
__device__ __forceinline__ float ex2f(float x) {
    float r;
    asm("ex2.approx.ftz.f32 %0, %1;" : "=f"(r) : "f"(x));
    return r;
}
__device__ __forceinline__ uint32_t hmul2(uint32_t a, uint32_t b) {
    uint32_t r;
    asm("mul.f16x2 %0, %1, %2;" : "=r"(r) : "r"(a), "r"(b));
    return r;
}
__device__ __forceinline__ uint32_t hmax2(uint32_t a, uint32_t b) {
    uint32_t r;
    asm("max.f16x2 %0, %1, %2;" : "=r"(r) : "r"(a), "r"(b));
    return r;
}
__device__ __forceinline__ uint32_t lds32(uint32_t a) {
    uint32_t r;
    asm volatile("ld.shared.b32 %0, [%1];" : "=r"(r) : "r"(a));
    return r;
}
__device__ __forceinline__ uint4 lds128(uint32_t a) {
    uint4 v;
    asm volatile("ld.shared.v4.b32 {%0,%1,%2,%3}, [%4];"
                 : "=r"(v.x), "=r"(v.y), "=r"(v.z), "=r"(v.w) : "r"(a));
    return v;
}
#define STS128(A, X, Y, Z, W) \
    asm volatile("st.shared.v4.b32 [%0], {%1,%2,%3,%4};" \
                 :: "r"(A), "r"(X), "r"(Y), "r"(Z), "r"(W) : "memory")
#define LDSM4(R0, R1, R2, R3, A) \
    asm volatile("ldmatrix.sync.aligned.m8n8.x4.shared.b16 {%0,%1,%2,%3}, [%4];" \
                 : "=r"(R0), "=r"(R1), "=r"(R2), "=r"(R3) : "r"(A))
#define MMAH(D, A0, A1, A2, A3, B0, B1) \
    asm volatile("mma.sync.aligned.m16n8k16.row.col.f32.f16.f16.f32 " \
                 "{%0,%1,%2,%3}, {%4,%5,%6,%7}, {%8,%9}, {%0,%1,%2,%3};" \
                 : "+f"((D)[0]), "+f"((D)[1]), "+f"((D)[2]), "+f"((D)[3]) \
                 : "r"(A0), "r"(A1), "r"(A2), "r"(A3), "r"(B0), "r"(B1))
#define CP16(dst, src) \
    asm volatile("cp.async.cg.shared.global [%0], [%1], 16;" :: "r"(dst), "l"(src) : "memory")
#define CP_COMMIT() asm volatile("cp.async.commit_group;" ::: "memory")
#define CP_WAIT(n)  asm volatile("cp.async.wait_group %0;" :: "n"(n) : "memory")
// producer-only named barrier: makes each producer's completed cp.async data
// visible to ALL producer threads before genP reads it cross-thread.
#define BAR_PROD()  asm volatile("bar.sync 1, 128;" ::: "memory")

// ---------------- Kernel 0: probe mask dtype --------------------------------
__global__ void detect_mask_fmt(const unsigned int* __restrict__ m) {
    int lane = threadIdx.x;
    bool not_i32 = false, not_f32 = false;
    for (int i = lane; i < 4096; i += 32) {
        unsigned int w = m[i];
        if (w > 1u) not_i32 = true;
        if (w != 0u && w != 0x3F800000u) not_f32 = true;
    }
    unsigned a = __ballot_sync(0xFFFFFFFFu, not_i32);
    unsigned b = __ballot_sync(0xFFFFFFFFu, not_f32);
    if (lane == 0) g_mask_fmt = (a == 0u) ? 1 : ((b == 0u) ? 2 : 0);
}

// ---------------- Kernel 0b: mask -> fp16 (1.0 / 0.0), [n][m] ----------------
__global__ void __launch_bounds__(256) mask_canon_h(const void* __restrict__ m) {
    int idx = blockIdx.x * 256 + threadIdx.x;    // 0 .. NN*NN/8-1
    int n  = idx >> 9;
    int m0 = (idx & 511) * 8;
    uint32_t h[4];
    if (g_mask_fmt != 0) {
        const uint4* p = (const uint4*)((const unsigned int*)m + (size_t)n * NN + m0);
        uint4 a = p[0], b = p[1];
        h[0] = (a.x ? 0x3C00u : 0u) | (a.y ? 0x3C000000u : 0u);
        h[1] = (a.z ? 0x3C00u : 0u) | (a.w ? 0x3C000000u : 0u);
        h[2] = (b.x ? 0x3C00u : 0u) | (b.y ? 0x3C000000u : 0u);
        h[3] = (b.z ? 0x3C00u : 0u) | (b.w ? 0x3C000000u : 0u);
    } else {
        uint2 a = *(const uint2*)((const unsigned char*)m + (size_t)n * NN + m0);
        unsigned w0 = a.x, w1 = a.y;
        h[0] = ((w0 & 0x000000FFu) ? 0x3C00u : 0u) | ((w0 & 0x0000FF00u) ? 0x3C000000u : 0u);
        h[1] = ((w0 & 0x00FF0000u) ? 0x3C00u : 0u) | ((w0 & 0xFF000000u) ? 0x3C000000u : 0u);
        h[2] = ((w1 & 0x000000FFu) ? 0x3C00u : 0u) | ((w1 & 0x0000FF00u) ? 0x3C000000u : 0u);
        h[3] = ((w1 & 0x00FF0000u) ? 0x3C00u : 0u) | ((w1 & 0xFF000000u) ? 0x3C000000u : 0u);
    }
    *(uint4*)(g_maskh + (size_t)n * NN + m0) = make_uint4(h[0], h[1], h[2], h[3]);
}

// ---------------- Kernel A: xe GEMM + fused hl + exp'd hr + fp16 transpose --
__global__ void __launch_bounds__(256) gemm_xe(const float* __restrict__ x,
                                               const float* __restrict__ W,
                                               const float* __restrict__ b,
                                               const float* __restrict__ al,
                                               const float* __restrict__ ar) {
    __shared__ float a_s[16][128];
    __shared__ float b_s[16][64];
    const int tid = threadIdx.x;
    const int tx = tid & 15;
    const int ty = tid >> 4;
    const int row0 = blockIdx.x * 128;
    const int k    = blockIdx.y;          // head
    const int col0 = k * 64;

    float acc[8][4];
#pragma unroll
    for (int i = 0; i < 8; i++)
#pragma unroll
        for (int j = 0; j < 4; j++) acc[i][j] = 0.0f;

    for (int k0 = 0; k0 < FF; k0 += 16) {
#pragma unroll
        for (int u = 0; u < 2; u++) {
            int f4 = tid * 2 + u;
            int r  = f4 >> 2;
            int c4 = f4 & 3;
            float4 v = *(const float4*)&x[(size_t)(row0 + r) * FF + k0 + c4 * 4];
            a_s[c4 * 4 + 0][r] = v.x; a_s[c4 * 4 + 1][r] = v.y;
            a_s[c4 * 4 + 2][r] = v.z; a_s[c4 * 4 + 3][r] = v.w;
        }
        {
            int o  = tid >> 2;
            int c4 = tid & 3;
            float4 v = *(const float4*)&W[(size_t)(col0 + o) * FF + k0 + c4 * 4];
            b_s[c4 * 4 + 0][o] = v.x; b_s[c4 * 4 + 1][o] = v.y;
            b_s[c4 * 4 + 2][o] = v.z; b_s[c4 * 4 + 3][o] = v.w;
        }
        __syncthreads();
#pragma unroll
        for (int kk = 0; kk < 16; kk++) {
            float a_f[8], b_f[4];
#pragma unroll
            for (int i = 0; i < 8; i++) a_f[i] = a_s[kk][ty * 8 + i];
#pragma unroll
            for (int j = 0; j < 4; j++) b_f[j] = b_s[kk][tx * 4 + j];
#pragma unroll
            for (int i = 0; i < 8; i++)
#pragma unroll
                for (int j = 0; j < 4; j++) acc[i][j] += a_f[i] * b_f[j];
        }
        __syncthreads();
    }
    float4 bias = *(const float4*)&b[col0 + tx * 4];
#pragma unroll
    for (int i = 0; i < 8; i++) {
        acc[i][0] += bias.x; acc[i][1] += bias.y;
        acc[i][2] += bias.z; acc[i][3] += bias.w;
    }
    // ---- fused hl/hr: partial dots, butterfly over tx ----
    float4 al4 = *(const float4*)&al[k * FPD + tx * 4];
    float4 ar4 = *(const float4*)&ar[k * FPD + tx * 4];
    float lsum[8], rsum[8];
#pragma unroll
    for (int i = 0; i < 8; i++) {
        float l = acc[i][0] * al4.x + acc[i][1] * al4.y + acc[i][2] * al4.z + acc[i][3] * al4.w;
        float r = acc[i][0] * ar4.x + acc[i][1] * ar4.y + acc[i][2] * ar4.z + acc[i][3] * ar4.w;
#pragma unroll
        for (int off = 8; off; off >>= 1) {
            l += __shfl_xor_sync(0xFFFFFFFFu, l, off);
            r += __shfl_xor_sync(0xFFFFFFFFu, r, off);
        }
        lsum[i] = l; rsum[i] = r;
    }
    if (tx == 0) {
#pragma unroll
        for (int i = 0; i < 8; i++)
            g_hl[k * NN + row0 + ty * 8 + i] = lsum[i] * LOG2E;
#pragma unroll
        for (int i2 = 0; i2 < 4; i2++) {
            float ra = rsum[2 * i2] * LOG2E, rb = rsum[2 * i2 + 1] * LOG2E;
            uint32_t bx = h16x2(ex2f(ra), ex2f(rb));
            uint32_t by = h16x2(ex2f(0.2f * ra), ex2f(0.2f * rb));
            g_hrB[k * (NN / 2) + (row0 + ty * 8) / 2 + i2] = make_uint2(bx, by);
        }
    }
    // ---- fp16 transpose: g_xeT_h[k][f][n] ----
#pragma unroll
    for (int j = 0; j < 4; j++) {
        uint32_t hp[4];
#pragma unroll
        for (int i2 = 0; i2 < 4; i2++)
            hp[i2] = h16x2(acc[2 * i2][j], acc[2 * i2 + 1][j]);
        size_t base = ((size_t)(k * FPD + tx * 4 + j)) * NN + row0 + ty * 8;
        *(uint4*)&g_xeT_h[base] = make_uint4(hp[0], hp[1], hp[2], hp[3]);
    }
}

// ---------------- Kernel C: warp-specialized fp16 mma attention --------------
// Warps 0-3 = PRODUCERS: P-fragments for chunk c+1 -> sts128 in A-frag layout.
// Warps 4-7 = CONSUMERS: lds128 A-frags + ldmatrix V + 18 MMAs per t.
// cp.async cross-thread visibility: CP_WAIT orders copies for the WAITING
// thread only -> producers run bar.sync(1,128) after every wait before genP.
#define MCH 64
#define NC  (NN / MCH)
#define V_STAGE_B  8192                       // 64 f-rows x 128B
#define MH_STAGE_B 16384                      // 128 n-rows x 128B
#define PF_STAGE_B 16384                      // 8 tiles x 4 t x 32 lanes x 16B
#define SMEM_ATTN  (3 * V_STAGE_B + 3 * MH_STAGE_B + 2 * PF_STAGE_B)   // 104 KB

__global__ void __launch_bounds__(256, 2) gat_attn_mma(float* __restrict__ out) {
    extern __shared__ __align__(16) char smem[];
    const uint32_t svb  = smem_u32(smem);
    const uint32_t smhb = svb + 3 * V_STAGE_B;
    const uint32_t spfb = smhb + 3 * MH_STAGE_B;

    const int tid  = threadIdx.x;
    const int lane = tid & 31;
    const int warp = tid >> 5;
    const int k    = blockIdx.y;
    const int n0   = blockIdx.x * 128;
    const int g    = lane >> 2;          // 0..7
    const int q    = lane & 3;           // 0..3
    const bool producer = (warp < 4);

    // ---- staging (producer threads only; 128 threads) ----
    auto stage_chunk = [&](int m0, int st) {
#pragma unroll
        for (int u = 0; u < 4; u++) {        // V: 512 x 16B
            int idx = u * 128 + tid;
            int f = idx >> 3, mo8 = (idx & 7) * 8;
            uint32_t dst = svb + st * V_STAGE_B + f * 128
                         + (((uint32_t)mo8 * 2) ^ ((uint32_t)(f & 7) << 4));
            CP16(dst, g_xeT_h + ((size_t)(k * FPD + f)) * NN + m0 + mo8);
        }
#pragma unroll
        for (int u = 0; u < 8; u++) {        // MH: 1024 x 16B
            int idx = u * 128 + tid;
            int row = idx >> 3, c16 = idx & 7;
            uint32_t dst = smhb + st * MH_STAGE_B + row * 128
                         + (((uint32_t)c16 * 16) ^ ((uint32_t)(row & 7) << 4));
            CP16(dst, g_maskh + ((size_t)(n0 + row)) * NN + m0 + c16 * 8);
        }
        CP_COMMIT();
    };

    // ---- producer state: per-row A factors for its 32 rows (2 tiles) ----
    uint32_t AhT[2][4];
    const uint32_t mswz = (uint32_t)g << 4;
    if (producer) {
#pragma unroll
        for (int ti = 0; ti < 2; ti++) {
            int rb = warp * 32 + ti * 16;
            float h0 = g_hl[k * NN + n0 + rb + g];
            float h1 = g_hl[k * NN + n0 + rb + 8 + g];
            AhT[ti][0] = h16x2(ex2f(h0), ex2f(h0));
            AhT[ti][1] = h16x2(ex2f(0.2f * h0), ex2f(0.2f * h0));
            AhT[ti][2] = h16x2(ex2f(h1), ex2f(h1));
            AhT[ti][3] = h16x2(ex2f(0.2f * h1), ex2f(0.2f * h1));
        }
    }

    // P-fragment generation for one chunk into pf stage pfst, mask stage st_mh
    auto genP = [&](int st_mh, int pfst, uint2 br) {
        const uint32_t mhbase = smhb + st_mh * MH_STAGE_B;
        const uint32_t pfbase = spfb + pfst * PF_STAGE_B;
#pragma unroll
        for (int t = 0; t < 4; t++) {
            const int j = 8 * t + q;
            uint32_t b0x = __shfl_sync(0xFFFFFFFFu, br.x, j);
            uint32_t b0y = __shfl_sync(0xFFFFFFFFu, br.y, j);
            uint32_t b1x = __shfl_sync(0xFFFFFFFFu, br.x, j + 4);
            uint32_t b1y = __shfl_sync(0xFFFFFFFFu, br.y, j + 4);
            uint32_t moff0 = ((uint32_t)(32 * t + 4 * q)) ^ mswz;
            uint32_t moff1 = moff0 ^ 16u;
#pragma unroll
            for (int ti = 0; ti < 2; ti++) {
                int rb = warp * 32 + ti * 16;
                uint32_t mh0b = mhbase + (rb + g) * 128;
                uint32_t mh1b = mhbase + (rb + 8 + g) * 128;
                uint32_t mh00 = lds32(mh0b + moff0);
                uint32_t mh01 = lds32(mh0b + moff1);
                uint32_t mh10 = lds32(mh1b + moff0);
                uint32_t mh11 = lds32(mh1b + moff1);
                uint32_t ah0 = hmul2(hmax2(hmul2(AhT[ti][0], b0x), hmul2(AhT[ti][1], b0y)), mh00);
                uint32_t ah1 = hmul2(hmax2(hmul2(AhT[ti][2], b0x), hmul2(AhT[ti][3], b0y)), mh10);
                uint32_t ah2 = hmul2(hmax2(hmul2(AhT[ti][0], b1x), hmul2(AhT[ti][1], b1y)), mh01);
                uint32_t ah3 = hmul2(hmax2(hmul2(AhT[ti][2], b1x), hmul2(AhT[ti][3], b1y)), mh11);
                STS128(pfbase + (uint32_t)(warp * 2 + ti) * 2048 + t * 512 + lane * 16,
                       ah0, ah1, ah2, ah3);
            }
        }
    };

    // ---- consumer state ----
    float d0[8][4], d1[8][4], drs0[4], drs1[4];
    const uint32_t lm_row  = ((lane & 16) >> 1) + (lane & 7);
    const uint32_t lm_koff = (lane & 8) ? 16u : 0u;
    const uint32_t vswz = (uint32_t)(lane & 7) << 4;
    const uint32_t onesB = (lane < 4) ? 0x3C003C00u : 0u;
    if (!producer) {
#pragma unroll
        for (int nt = 0; nt < 8; nt++)
#pragma unroll
            for (int e = 0; e < 4; e++) { d0[nt][e] = 0.0f; d1[nt][e] = 0.0f; }
#pragma unroll
        for (int e = 0; e < 4; e++) { drs0[e] = 0.0f; drs1[e] = 0.0f; }
    }

    uint2 breg_next;
    // ---- prologue ----
    if (producer) {
        stage_chunk(0, 0);
        stage_chunk(MCH, 1);
        CP_WAIT(1);                                   // G0 complete (this thread)
        BAR_PROD();                                   // make G0 visible to ALL producers
        uint2 b0 = g_hrB[k * (NN / 2) + lane];        // chunk 0
        breg_next = g_hrB[k * (NN / 2) + 32 + lane];  // chunk 1
        genP(0, 0, b0);
    }
    __syncthreads();

#pragma unroll 1
    for (int c = 0; c < NC; c++) {
        if (producer) {
            if (c + 1 < NC) {
                if (c + 2 < NC) { stage_chunk((c + 2) * MCH, (c + 2) % 3); CP_WAIT(1); }
                else            { CP_WAIT(0); }
                BAR_PROD();                           // G(c+1) visible to all producers
                uint2 bcur = breg_next;
                if (c + 2 < NC) breg_next = g_hrB[k * (NN / 2) + (c + 2) * 32 + lane];
                genP((c + 1) % 3, (c + 1) & 1, bcur);
            }
        } else {
            const int cw = warp - 4;
            const uint32_t sv  = svb + (c % 3) * V_STAGE_B;
            const uint32_t pfb = spfb + (c & 1) * PF_STAGE_B + (uint32_t)(cw * 2) * 2048;
#pragma unroll
            for (int t = 0; t < 4; t++) {
                const uint32_t voff = ((uint32_t)(32 * t) + lm_koff) ^ vswz;
                uint32_t vA[4], vB[4], vC[4], vD[4];
#pragma unroll
                for (int pr = 0; pr < 4; pr++)
                    LDSM4(vA[pr], vB[pr], vC[pr], vD[pr], sv + (pr * 16 + lm_row) * 128 + voff);
                uint4 a0 = lds128(pfb + t * 512 + lane * 16);
                uint4 a1 = lds128(pfb + 2048 + t * 512 + lane * 16);
#pragma unroll
                for (int pr = 0; pr < 4; pr++) {
                    MMAH(d0[2 * pr],     a0.x, a0.y, a0.z, a0.w, vA[pr], vB[pr]);
                    MMAH(d0[2 * pr + 1], a0.x, a0.y, a0.z, a0.w, vC[pr], vD[pr]);
                }
                MMAH(drs0, a0.x, a0.y, a0.z, a0.w, onesB, onesB);
#pragma unroll
                for (int pr = 0; pr < 4; pr++) {
                    MMAH(d1[2 * pr],     a1.x, a1.y, a1.z, a1.w, vA[pr], vB[pr]);
                    MMAH(d1[2 * pr + 1], a1.x, a1.y, a1.z, a1.w, vC[pr], vD[pr]);
                }
                MMAH(drs1, a1.x, a1.y, a1.z, a1.w, onesB, onesB);
            }
        }
        __syncthreads();
    }

    // ---- epilogue (consumers): rowsums, normalize, double-ELU, store ----
    if (!producer) {
        const int cw = warp - 4;
#pragma unroll
        for (int ti = 0; ti < 2; ti++) {
            float (*d)[4] = ti ? d1 : d0;
            float* drs = ti ? drs1 : drs0;
            const int rb = cw * 32 + ti * 16;
            const float rv0 = __shfl_sync(0xFFFFFFFFu, drs[0], 0, 4);
            const float rv1 = __shfl_sync(0xFFFFFFFFu, drs[2], 0, 4);
            const float i0 = 1.0f / rv0;
            const float i1 = 1.0f / rv1;
            float* o0p = out + (size_t)(n0 + rb + g) * KFP + k * FPD + 2 * q;
            float* o1p = out + (size_t)(n0 + rb + 8 + g) * KFP + k * FPD + 2 * q;
#pragma unroll
            for (int nt = 0; nt < 8; nt++) {
                float z0 = d[nt][0] * i0, z1 = d[nt][1] * i0;
                float z2 = d[nt][2] * i1, z3 = d[nt][3] * i1;
                z0 = z0 > 0.f ? z0 : expm1f(z0); z0 = z0 > 0.f ? z0 : expm1f(z0);
                z1 = z1 > 0.f ? z1 : expm1f(z1); z1 = z1 > 0.f ? z1 : expm1f(z1);
                z2 = z2 > 0.f ? z2 : expm1f(z2); z2 = z2 > 0.f ? z2 : expm1f(z2);
                z3 = z3 > 0.f ? z3 : expm1f(z3); z3 = z3 > 0.f ? z3 : expm1f(z3);
                *(float2*)(o0p + nt * 8) = make_float2(z0, z1);
                *(float2*)(o1p + nt * 8) = make_float2(z2, z3);
            }
        }
    }
}

// ---------------- optional: mask passthrough as float -----------------------
__global__ void mask_to_float(float* __restrict__ o, int n4) {
    int i = blockIdx.x * blockDim.x + threadIdx.x;
    if (i < n4) {
        uint2 v = *(const uint2*)(g_maskh + (size_t)i * 4);
        float4 f;
        f.x = (v.x & 0xFFFFu)     ? 1.0f : 0.0f;
        f.y = (v.x >> 16)         ? 1.0f : 0.0f;
        f.z = (v.y & 0xFFFFu)     ? 1.0f : 0.0f;
        f.w = (v.y >> 16)         ? 1.0f : 0.0f;
        *(float4*)(o + (size_t)i * 4) = f;
    }
}

// ---------------- launch -----------------------------------------------------
extern "C" void kernel_launch(void* const* d_in, const int* in_sizes, int n_in,
                              void* d_out, int out_size) {
    const float* x  = (const float*)d_in[0];
    const float* W  = (const float*)d_in[1];
    const float* b  = (const float*)d_in[2];
    const float* al = (const float*)d_in[3];
    const float* ar = (const float*)d_in[4];
    const void*  m  = d_in[5];
    float* out = (float*)d_out;

    cudaFuncSetAttribute(gat_attn_mma, cudaFuncAttributeMaxDynamicSharedMemorySize, SMEM_ATTN);

    detect_mask_fmt<<<1, 32>>>((const unsigned int*)m);
    mask_canon_h<<<(NN * NN / 8) / 256, 256>>>(m);
    gemm_xe<<<dim3(32, 8), 256>>>(x, W, b, al, ar);
    gat_attn_mma<<<dim3(32, 8), 256, SMEM_ATTN>>>(out);

    const int OUT_ELEMS  = NN * KFP;
    const int MASK_ELEMS = NN * NN;
    if (out_size >= OUT_ELEMS + MASK_ELEMS) {
        mask_to_float<<<(MASK_ELEMS / 4 + 255) / 256, 256>>>(out + OUT_ELEMS, MASK_ELEMS / 4);
    }
}

// round 13
// speedup vs baseline: 1.0237x; 1.0237x over previous
#include <cuda_runtime.h>
#include <cuda_fp16.h>
#include <cstdint>

#define NN   4096
#define FF   256
#define KH   8
#define FPD  64
#define KFP  512   // K*FP
#define LOG2E 1.4426950408889634f

// ---------------- scratch (static device globals; no allocation) -------------
__device__ float g_hl[KH * NN];                   // hl[k][n] * log2(e)
__device__ uint2 g_hrB[KH * NN / 2];              // packed { fp16x2(B,B'), fp16x2(B2,B2') }
__device__ int g_mask_fmt;                        // 0=uint8, else 4-byte words
__device__ unsigned short g_maskh[NN * NN];       // 32 MB fp16 mask (1.0 / 0.0)
__device__ unsigned short g_xeT_h[KH * FPD * NN]; // 4 MB: fp16(xe)[k][f][n]

// =================== helpers (baseline PTX only) ============================
__device__ __forceinline__ uint32_t smem_u32(const void* p) {
    uint32_t a;
    asm("{ .reg .u64 t; cvta.to.shared.u64 t, %1; cvt.u32.u64 %0, t; }" : "=r"(a) : "l"(p));
    return a;
}
__device__ __forceinline__ uint32_t h16x2(float x, float y) {
    uint32_t r;
    asm("cvt.rn.f16x2.f32 %0, %1, %2;" : "=r"(r) : "f"(y), "f"(x));
    return r;
}
__device__ __forceinline__ float ex2f(float x) {
    float r;
    asm("ex2.approx.ftz.f32 %0, %1;" : "=f"(r) : "f"(x));
    return r;
}
__device__ __forceinline__ uint32_t hmul2(uint32_t a, uint32_t b) {
    uint32_t r;
    asm("mul.f16x2 %0, %1, %2;" : "=r"(r) : "r"(a), "r"(b));
    return r;
}
__device__ __forceinline__ uint32_t hmax2(uint32_t a, uint32_t b) {
    uint32_t r;
    asm("max.f16x2 %0, %1, %2;" : "=r"(r) : "r"(a), "r"(b));
    return r;
}
__device__ __forceinline__ uint32_t lds32(uint32_t a) {
    uint32_t r;
    asm volatile("ld.shared.b32 %0, [%1];" : "=r"(r) : "r"(a));
    return r;
}
#define LDSM4(R0, R1, R2, R3, A) \
    asm volatile("ldmatrix.sync.aligned.m8n8.x4.shared.b16 {%0,%1,%2,%3}, [%4];" \
                 : "=r"(R0), "=r"(R1), "=r"(R2), "=r"(R3) : "r"(A))
#define MMAH(D, A0, A1, A2, A3, B0, B1) \
    asm volatile("mma.sync.aligned.m16n8k16.row.col.f32.f16.f16.f32 " \
                 "{%0,%1,%2,%3}, {%4,%5,%6,%7}, {%8,%9}, {%0,%1,%2,%3};" \
                 : "+f"((D)[0]), "+f"((D)[1]), "+f"((D)[2]), "+f"((D)[3]) \
                 : "r"(A0), "r"(A1), "r"(A2), "r"(A3), "r"(B0), "r"(B1))
#define CP16(dst, src) \
    asm volatile("cp.async.cg.shared.global [%0], [%1], 16;" :: "r"(dst), "l"(src) : "memory")
#define CP_COMMIT() asm volatile("cp.async.commit_group;" ::: "memory")
#define CP_WAIT(n)  asm volatile("cp.async.wait_group %0;" :: "n"(n) : "memory")

// ---------------- Kernel 0: probe mask dtype --------------------------------
__global__ void detect_mask_fmt(const unsigned int* __restrict__ m) {
    int lane = threadIdx.x;
    bool not_i32 = false, not_f32 = false;
    for (int i = lane; i < 4096; i += 32) {
        unsigned int w = m[i];
        if (w > 1u) not_i32 = true;
        if (w != 0u && w != 0x3F800000u) not_f32 = true;
    }
    unsigned a = __ballot_sync(0xFFFFFFFFu, not_i32);
    unsigned b = __ballot_sync(0xFFFFFFFFu, not_f32);
    if (lane == 0) g_mask_fmt = (a == 0u) ? 1 : ((b == 0u) ? 2 : 0);
}

// ---------------- Fused kernel: GEMM(+hl/hrB+fp16 transpose) || mask canon ---
// Blocks [0,256): xe GEMM for (row-block, head) exactly as before.
// Blocks [256, 256+2048): mask canonicalization — each thread converts 32
// mask elements: writes fp16 0/1 to g_maskh AND (if mout) float 0/1 to the
// second output. Memory-bound work overlaps the FFMA-bound GEMM blocks.
#define CANON_BLKS 2048   // 2048 * 256 thr * 32 elems = 16M = NN*NN

__global__ void __launch_bounds__(256) fused_gemm_canon(
        const float* __restrict__ x, const float* __restrict__ W,
        const float* __restrict__ b, const float* __restrict__ al,
        const float* __restrict__ ar, const void* __restrict__ m,
        float* __restrict__ mout /* may be null */) {
    if (blockIdx.x >= 256) {
        // ================= mask canon (+ optional float output) =============
        int idx = (blockIdx.x - 256) * 256 + threadIdx.x;   // 0..524287
        int e0 = idx * 32;
        int n  = e0 >> 12;
        int m0 = e0 & 4095;
        uint32_t h[16];
        float f[32];
        if (g_mask_fmt != 0) {     // 4-byte words (int32 or float32)
            const uint4* p = (const uint4*)((const unsigned int*)m + (size_t)n * NN + m0);
            uint4 w[8];
#pragma unroll
            for (int i = 0; i < 8; i++) w[i] = p[i];
#pragma unroll
            for (int i = 0; i < 8; i++) {
                h[2 * i]     = (w[i].x ? 0x3C00u : 0u) | (w[i].y ? 0x3C000000u : 0u);
                h[2 * i + 1] = (w[i].z ? 0x3C00u : 0u) | (w[i].w ? 0x3C000000u : 0u);
                f[4 * i + 0] = w[i].x ? 1.0f : 0.0f;
                f[4 * i + 1] = w[i].y ? 1.0f : 0.0f;
                f[4 * i + 2] = w[i].z ? 1.0f : 0.0f;
                f[4 * i + 3] = w[i].w ? 1.0f : 0.0f;
            }
        } else {                   // packed uint8
            const uint4* p = (const uint4*)((const unsigned char*)m + (size_t)n * NN + m0);
            uint4 w01 = p[0], w23 = p[1];
            unsigned wv[8] = {w01.x, w01.y, w01.z, w01.w, w23.x, w23.y, w23.z, w23.w};
#pragma unroll
            for (int i = 0; i < 8; i++) {
                unsigned wq = wv[i];
                h[2 * i]     = ((wq & 0x000000FFu) ? 0x3C00u : 0u) | ((wq & 0x0000FF00u) ? 0x3C000000u : 0u);
                h[2 * i + 1] = ((wq & 0x00FF0000u) ? 0x3C00u : 0u) | ((wq & 0xFF000000u) ? 0x3C000000u : 0u);
                f[4 * i + 0] = (wq & 0x000000FFu) ? 1.0f : 0.0f;
                f[4 * i + 1] = (wq & 0x0000FF00u) ? 1.0f : 0.0f;
                f[4 * i + 2] = (wq & 0x00FF0000u) ? 1.0f : 0.0f;
                f[4 * i + 3] = (wq & 0xFF000000u) ? 1.0f : 0.0f;
            }
        }
        uint4* hdst = (uint4*)(g_maskh + (size_t)n * NN + m0);
#pragma unroll
        for (int i = 0; i < 4; i++)
            hdst[i] = make_uint4(h[4 * i], h[4 * i + 1], h[4 * i + 2], h[4 * i + 3]);
        if (mout) {
            float4* fdst = (float4*)(mout + (size_t)n * NN + m0);
#pragma unroll
            for (int i = 0; i < 8; i++)
                fdst[i] = make_float4(f[4 * i], f[4 * i + 1], f[4 * i + 2], f[4 * i + 3]);
        }
        return;
    }

    // ===================== xe GEMM (blocks 0..255) ==========================
    __shared__ float a_s[16][128];
    __shared__ float b_s[16][64];
    const int gb  = blockIdx.x;
    const int tid = threadIdx.x;
    const int tx = tid & 15;
    const int ty = tid >> 4;
    const int row0 = (gb >> 3) * 128;
    const int k    = gb & 7;              // head
    const int col0 = k * 64;

    float acc[8][4];
#pragma unroll
    for (int i = 0; i < 8; i++)
#pragma unroll
        for (int j = 0; j < 4; j++) acc[i][j] = 0.0f;

    for (int k0 = 0; k0 < FF; k0 += 16) {
#pragma unroll
        for (int u = 0; u < 2; u++) {
            int f4 = tid * 2 + u;
            int r  = f4 >> 2;
            int c4 = f4 & 3;
            float4 v = *(const float4*)&x[(size_t)(row0 + r) * FF + k0 + c4 * 4];
            a_s[c4 * 4 + 0][r] = v.x; a_s[c4 * 4 + 1][r] = v.y;
            a_s[c4 * 4 + 2][r] = v.z; a_s[c4 * 4 + 3][r] = v.w;
        }
        {
            int o  = tid >> 2;
            int c4 = tid & 3;
            float4 v = *(const float4*)&W[(size_t)(col0 + o) * FF + k0 + c4 * 4];
            b_s[c4 * 4 + 0][o] = v.x; b_s[c4 * 4 + 1][o] = v.y;
            b_s[c4 * 4 + 2][o] = v.z; b_s[c4 * 4 + 3][o] = v.w;
        }
        __syncthreads();
#pragma unroll
        for (int kk = 0; kk < 16; kk++) {
            float a_f[8], b_f[4];
#pragma unroll
            for (int i = 0; i < 8; i++) a_f[i] = a_s[kk][ty * 8 + i];
#pragma unroll
            for (int j = 0; j < 4; j++) b_f[j] = b_s[kk][tx * 4 + j];
#pragma unroll
            for (int i = 0; i < 8; i++)
#pragma unroll
                for (int j = 0; j < 4; j++) acc[i][j] += a_f[i] * b_f[j];
        }
        __syncthreads();
    }
    float4 bias = *(const float4*)&b[col0 + tx * 4];
#pragma unroll
    for (int i = 0; i < 8; i++) {
        acc[i][0] += bias.x; acc[i][1] += bias.y;
        acc[i][2] += bias.z; acc[i][3] += bias.w;
    }
    // ---- fused hl/hr: partial dots, butterfly over tx ----
    float4 al4 = *(const float4*)&al[k * FPD + tx * 4];
    float4 ar4 = *(const float4*)&ar[k * FPD + tx * 4];
    float lsum[8], rsum[8];
#pragma unroll
    for (int i = 0; i < 8; i++) {
        float l = acc[i][0] * al4.x + acc[i][1] * al4.y + acc[i][2] * al4.z + acc[i][3] * al4.w;
        float r = acc[i][0] * ar4.x + acc[i][1] * ar4.y + acc[i][2] * ar4.z + acc[i][3] * ar4.w;
#pragma unroll
        for (int off = 8; off; off >>= 1) {
            l += __shfl_xor_sync(0xFFFFFFFFu, l, off);
            r += __shfl_xor_sync(0xFFFFFFFFu, r, off);
        }
        lsum[i] = l; rsum[i] = r;
    }
    if (tx == 0) {
#pragma unroll
        for (int i = 0; i < 8; i++)
            g_hl[k * NN + row0 + ty * 8 + i] = lsum[i] * LOG2E;
#pragma unroll
        for (int i2 = 0; i2 < 4; i2++) {
            float ra = rsum[2 * i2] * LOG2E, rb = rsum[2 * i2 + 1] * LOG2E;
            uint32_t bx = h16x2(ex2f(ra), ex2f(rb));
            uint32_t by = h16x2(ex2f(0.2f * ra), ex2f(0.2f * rb));
            g_hrB[k * (NN / 2) + (row0 + ty * 8) / 2 + i2] = make_uint2(bx, by);
        }
    }
    // ---- fp16 transpose: g_xeT_h[k][f][n] ----
#pragma unroll
    for (int j = 0; j < 4; j++) {
        uint32_t hp[4];
#pragma unroll
        for (int i2 = 0; i2 < 4; i2++)
            hp[i2] = h16x2(acc[2 * i2][j], acc[2 * i2 + 1][j]);
        size_t base = ((size_t)(k * FPD + tx * 4 + j)) * NN + row0 + ty * 8;
        *(uint4*)&g_xeT_h[base] = make_uint4(hp[0], hp[1], hp[2], hp[3]);
    }
}

// ---------------- Kernel C: attention, fp16 mma, 4-stage cp.async pipeline ---
// (R10 kernel, unchanged — known-good 84.1us.)
// p = 2^max(s, 0.2s) = max(A*B, A2*B2); A per-row (regs), B per-m (shfl bcast),
// mask = fp16 0/1 multiplied in. 4 SMEM stages, wait_group 2.
#define MCH 64
#define NCHUNK (NN / MCH)
#define V_STAGE_B  8192     // 64 f-rows x 128B
#define MH_STAGE_B 16384    // 128 n-rows x 128B
#define SMEM_ATTN  (4 * (V_STAGE_B + MH_STAGE_B))   // 96 KB dynamic

__global__ void __launch_bounds__(256, 2) gat_attn_mma(float* __restrict__ out) {
    extern __shared__ __align__(16) char smem[];
    const uint32_t svb  = smem_u32(smem);                    // 4 x V stages
    const uint32_t smhb = svb + 4 * V_STAGE_B;               // 4 x MH stages

    const int tid  = threadIdx.x;
    const int lane = tid & 31;
    const int warp = tid >> 5;
    const int k    = blockIdx.y;
    const int n0   = blockIdx.x * 128;
    const int g    = lane >> 2;          // 0..7
    const int q    = lane & 3;           // 0..3
    const int r0   = warp * 16 + g;
    const int r1   = r0 + 8;

    const float hl2_0 = g_hl[k * NN + n0 + r0];
    const float hl2_1 = g_hl[k * NN + n0 + r1];
    const uint32_t Ah0  = h16x2(ex2f(hl2_0), ex2f(hl2_0));
    const uint32_t A2h0 = h16x2(ex2f(0.2f * hl2_0), ex2f(0.2f * hl2_0));
    const uint32_t Ah1  = h16x2(ex2f(hl2_1), ex2f(hl2_1));
    const uint32_t A2h1 = h16x2(ex2f(0.2f * hl2_1), ex2f(0.2f * hl2_1));
    const uint32_t onesB = (lane < 4) ? 0x3C003C00u : 0u;    // rowsum B-fragment

    float d[8][4];
#pragma unroll
    for (int nt = 0; nt < 8; nt++)
#pragma unroll
        for (int e = 0; e < 4; e++) d[nt][e] = 0.0f;
    float drs[4] = {0.f, 0.f, 0.f, 0.f};

    const uint32_t lm_row  = ((lane & 16) >> 1) + (lane & 7);   // 0..15
    const uint32_t lm_koff = (lane & 8) ? 16u : 0u;
    const uint32_t vswz = (uint32_t)(lane & 7) << 4;
    const uint32_t mswz = (uint32_t)g << 4;

    uint2 breg, breg_next;

    auto stage_chunk = [&](int m0, int st) {
#pragma unroll
        for (int u = 0; u < 2; u++) {        // V: 512 x 16B
            int idx = u * 256 + tid;
            int f = idx >> 3, mo8 = (idx & 7) * 8;
            uint32_t dst = svb + st * V_STAGE_B + f * 128
                         + (((uint32_t)mo8 * 2) ^ ((uint32_t)(f & 7) << 4));
            CP16(dst, g_xeT_h + ((size_t)(k * FPD + f)) * NN + m0 + mo8);
        }
#pragma unroll
        for (int u = 0; u < 4; u++) {        // MH: 1024 x 16B
            int idx = u * 256 + tid;
            int row = idx >> 3, c16 = idx & 7;
            uint32_t dst = smhb + st * MH_STAGE_B + row * 128
                         + (((uint32_t)c16 * 16) ^ ((uint32_t)(row & 7) << 4));
            CP16(dst, g_maskh + ((size_t)(n0 + row)) * NN + m0 + c16 * 8);
        }
        CP_COMMIT();
    };

    // ---- prologue: stage chunks 0,1,2 ----
    stage_chunk(0, 0);
    stage_chunk(MCH, 1);
    stage_chunk(2 * MCH, 2);
    breg = g_hrB[k * (NN / 2) + lane];

#pragma unroll 1
    for (int c = 0; c < NCHUNK; c++) {
        const int st = c & 3;
        CP_WAIT(2);
        __syncthreads();
        if (c + 3 < NCHUNK) stage_chunk((c + 3) * MCH, (c + 3) & 3);
        if (c + 1 < NCHUNK) breg_next = g_hrB[k * (NN / 2) + (c + 1) * 32 + lane];

        const uint32_t sv   = svb + st * V_STAGE_B;
        const uint32_t mh0b = smhb + st * MH_STAGE_B + r0 * 128;
        const uint32_t mh1b = smhb + st * MH_STAGE_B + r1 * 128;

#pragma unroll
        for (int t = 0; t < 4; t++) {
            const int j = 8 * t + q;
            uint32_t b0x = __shfl_sync(0xFFFFFFFFu, breg.x, j);
            uint32_t b0y = __shfl_sync(0xFFFFFFFFu, breg.y, j);
            uint32_t b1x = __shfl_sync(0xFFFFFFFFu, breg.x, j + 4);
            uint32_t b1y = __shfl_sync(0xFFFFFFFFu, breg.y, j + 4);
            uint32_t moff0 = ((uint32_t)(32 * t + 4 * q)) ^ mswz;
            uint32_t moff1 = moff0 ^ 16u;
            uint32_t mh00 = lds32(mh0b + moff0);
            uint32_t mh01 = lds32(mh0b + moff1);
            uint32_t mh10 = lds32(mh1b + moff0);
            uint32_t mh11 = lds32(mh1b + moff1);
            uint32_t ah0 = hmul2(hmax2(hmul2(Ah0, b0x), hmul2(A2h0, b0y)), mh00);
            uint32_t ah1 = hmul2(hmax2(hmul2(Ah1, b0x), hmul2(A2h1, b0y)), mh10);
            uint32_t ah2 = hmul2(hmax2(hmul2(Ah0, b1x), hmul2(A2h0, b1y)), mh01);
            uint32_t ah3 = hmul2(hmax2(hmul2(Ah1, b1x), hmul2(A2h1, b1y)), mh11);

            const uint32_t voff = ((uint32_t)(32 * t) + lm_koff) ^ vswz;
            uint32_t vA[4], vB[4], vC[4], vD[4];
#pragma unroll
            for (int pr = 0; pr < 4; pr++)
                LDSM4(vA[pr], vB[pr], vC[pr], vD[pr], sv + (pr * 16 + lm_row) * 128 + voff);
#pragma unroll
            for (int pr = 0; pr < 4; pr++) {
                MMAH(d[2 * pr],     ah0, ah1, ah2, ah3, vA[pr], vB[pr]);
                MMAH(d[2 * pr + 1], ah0, ah1, ah2, ah3, vC[pr], vD[pr]);
            }
            MMAH(drs, ah0, ah1, ah2, ah3, onesB, onesB);
        }
        breg = breg_next;
    }

    // ---- epilogue: rowsums from ones-column, normalize, double-ELU, store ----
    const float rv0 = __shfl_sync(0xFFFFFFFFu, drs[0], 0, 4);
    const float rv1 = __shfl_sync(0xFFFFFFFFu, drs[2], 0, 4);
    const float i0 = 1.0f / rv0;
    const float i1 = 1.0f / rv1;
    float* o0p = out + (size_t)(n0 + r0) * KFP + k * FPD + 2 * q;
    float* o1p = out + (size_t)(n0 + r1) * KFP + k * FPD + 2 * q;
#pragma unroll
    for (int nt = 0; nt < 8; nt++) {
        float z0 = d[nt][0] * i0, z1 = d[nt][1] * i0;
        float z2 = d[nt][2] * i1, z3 = d[nt][3] * i1;
        z0 = z0 > 0.f ? z0 : expm1f(z0); z0 = z0 > 0.f ? z0 : expm1f(z0);
        z1 = z1 > 0.f ? z1 : expm1f(z1); z1 = z1 > 0.f ? z1 : expm1f(z1);
        z2 = z2 > 0.f ? z2 : expm1f(z2); z2 = z2 > 0.f ? z2 : expm1f(z2);
        z3 = z3 > 0.f ? z3 : expm1f(z3); z3 = z3 > 0.f ? z3 : expm1f(z3);
        *(float2*)(o0p + nt * 8) = make_float2(z0, z1);
        *(float2*)(o1p + nt * 8) = make_float2(z2, z3);
    }
}

// ---------------- launch -----------------------------------------------------
extern "C" void kernel_launch(void* const* d_in, const int* in_sizes, int n_in,
                              void* d_out, int out_size) {
    const float* x  = (const float*)d_in[0];
    const float* W  = (const float*)d_in[1];
    const float* b  = (const float*)d_in[2];
    const float* al = (const float*)d_in[3];
    const float* ar = (const float*)d_in[4];
    const void*  m  = d_in[5];
    float* out = (float*)d_out;

    cudaFuncSetAttribute(gat_attn_mma, cudaFuncAttributeMaxDynamicSharedMemorySize, SMEM_ATTN);

    const int OUT_ELEMS  = NN * KFP;
    const int MASK_ELEMS = NN * NN;
    float* mout = (out_size >= OUT_ELEMS + MASK_ELEMS) ? (out + OUT_ELEMS) : nullptr;

    detect_mask_fmt<<<1, 32>>>((const unsigned int*)m);
    fused_gemm_canon<<<256 + CANON_BLKS, 256>>>(x, W, b, al, ar, m, mout);
    gat_attn_mma<<<dim3(32, 8), 256, SMEM_ATTN>>>(out);
}